// round 5
// baseline (speedup 1.0000x reference)
#include <cuda_runtime.h>
#include <cuda_bf16.h>
#include <cstdint>

// Problem constants (from reference)
#define N_NODES 100000
#define D_IN    256
#define D_OUT   128

// Scratch for support = x @ W   (51.2 MB, __device__ global per harness rules)
__device__ float g_support[(size_t)N_NODES * D_OUT];

// ---------------------------------------------------------------------------
// SGEMM: C[M,128] = A[M,256] @ B[256,128], fp32, 128x128 block tile, 8x8 thread tile
// ---------------------------------------------------------------------------
#define BM 128
#define BN 128
#define BK 16

__global__ __launch_bounds__(256, 2)
void gemm_kernel(const float* __restrict__ A, const float* __restrict__ B,
                 float* __restrict__ C, int M) {
    __shared__ float As[BK][BM];   // transposed A tile
    __shared__ float Bs[BK][BN];

    const int tid  = threadIdx.x;
    const int row0 = blockIdx.x * BM;

    const int tx = tid % 16;       // 0..15 -> col group
    const int ty = tid / 16;       // 0..15 -> row group

    // Global-load mapping
    const int aRow = tid / 4;            // 0..63 (two passes: +0, +64)
    const int aCol = (tid % 4) * 4;      // 0,4,8,12 within BK
    const int bRow = tid / 32;           // 0..7 (two passes: +0, +8)
    const int bCol = (tid % 32) * 4;     // 0..124

    float acc[8][8];
    #pragma unroll
    for (int i = 0; i < 8; i++)
        #pragma unroll
        for (int j = 0; j < 8; j++) acc[i][j] = 0.0f;

    for (int k0 = 0; k0 < D_IN; k0 += BK) {
        // Load A tile (128x16), store transposed into As[k][m]
        #pragma unroll
        for (int i = 0; i < 2; i++) {
            int r  = aRow + i * 64;
            int gr = row0 + r;
            float4 v = make_float4(0.f, 0.f, 0.f, 0.f);
            if (gr < M)
                v = *(const float4*)(A + (size_t)gr * D_IN + k0 + aCol);
            As[aCol + 0][r] = v.x;
            As[aCol + 1][r] = v.y;
            As[aCol + 2][r] = v.z;
            As[aCol + 3][r] = v.w;
        }
        // Load B tile (16x128), row-major direct
        #pragma unroll
        for (int i = 0; i < 2; i++) {
            int r = bRow + i * 8;
            float4 v = *(const float4*)(B + (size_t)(k0 + r) * D_OUT + bCol);
            *(float4*)&Bs[r][bCol] = v;
        }
        __syncthreads();

        #pragma unroll
        for (int k = 0; k < BK; k++) {
            float a[8], b[8];
            *(float4*)&a[0] = *(const float4*)&As[k][ty * 8];
            *(float4*)&a[4] = *(const float4*)&As[k][ty * 8 + 4];
            *(float4*)&b[0] = *(const float4*)&Bs[k][tx * 8];
            *(float4*)&b[4] = *(const float4*)&Bs[k][tx * 8 + 4];
            #pragma unroll
            for (int i = 0; i < 8; i++)
                #pragma unroll
                for (int j = 0; j < 8; j++)
                    acc[i][j] += a[i] * b[j];
        }
        __syncthreads();
    }

    // Store 8x8 per thread (float4 x2 per row)
    #pragma unroll
    for (int i = 0; i < 8; i++) {
        int gr = row0 + ty * 8 + i;
        if (gr < M) {
            float* cp = C + (size_t)gr * D_OUT + tx * 8;
            *(float4*)(cp)     = *(float4*)&acc[i][0];
            *(float4*)(cp + 4) = *(float4*)&acc[i][4];
        }
    }
}

// ---------------------------------------------------------------------------
// Scatter: one warp per edge. Lane l handles floats [4l, 4l+4) of the 128-dim row.
// gather support[src], scale by w, red.global.add.v4.f32 into out[dst].
// ---------------------------------------------------------------------------
__global__ __launch_bounds__(256)
void scatter_kernel(const float* __restrict__ support,
                    const int*   __restrict__ src,
                    const int*   __restrict__ dst,
                    const float* __restrict__ ew,
                    float*       __restrict__ out,
                    int nE) {
    int gw   = (int)((blockIdx.x * (unsigned)blockDim.x + threadIdx.x) >> 5);
    int lane = threadIdx.x & 31;
    if (gw >= nE) return;

    int   s  = __ldg(src + gw);
    int   d  = __ldg(dst + gw);
    float wt = __ldg(ew  + gw);

    float4 v = *(const float4*)(support + (size_t)s * D_OUT + lane * 4);
    v.x *= wt; v.y *= wt; v.z *= wt; v.w *= wt;

    float* p = out + (size_t)d * D_OUT + lane * 4;
    asm volatile("red.global.add.v4.f32 [%0], {%1, %2, %3, %4};"
                 :: "l"(p), "f"(v.x), "f"(v.y), "f"(v.z), "f"(v.w)
                 : "memory");
}

// ---------------------------------------------------------------------------
// Launcher
// Inputs (metadata order): x[f32 N*256], edge_src[i32 E], edge_dst[i32 E],
//                          edge_weight[f32 E], W[f32 256*128]
// Output: out[f32 N*128]
// ---------------------------------------------------------------------------
extern "C" void kernel_launch(void* const* d_in, const int* in_sizes, int n_in,
                              void* d_out, int out_size) {
    const float* x   = (const float*)d_in[0];
    const int*   esrc = (const int*)d_in[1];
    const int*   edst = (const int*)d_in[2];
    const float* ew  = (const float*)d_in[3];
    const float* W   = (const float*)d_in[4];
    float* out = (float*)d_out;

    const int nE = in_sizes[1];

    float* support;
    cudaGetSymbolAddress((void**)&support, g_support);

    // 1) zero output (memset node — graph-capturable)
    cudaMemsetAsync(d_out, 0, (size_t)out_size * sizeof(float));

    // 2) support = x @ W
    {
        dim3 grid((N_NODES + BM - 1) / BM);
        gemm_kernel<<<grid, 256>>>(x, W, support, N_NODES);
    }

    // 3) out[dst] += w * support[src]   (one warp per edge)
    {
        long long totalThreads = (long long)nE * 32;
        int blocks = (int)((totalThreads + 255) / 256);
        scatter_kernel<<<blocks, 256>>>(support, esrc, edst, ew, out, nE);
    }
}